// round 8
// baseline (speedup 1.0000x reference)
#include <cuda_runtime.h>
#include <cuda_fp16.h>
#include <cstdint>

// Problem dims
#define BB   2048
#define NN   196
#define DD   1024
#define DC   512

// ---------------------------------------------------------------------------
// Scratch (device globals; no allocation allowed)
// ---------------------------------------------------------------------------
__device__ float  g_t[(size_t)BB * DD];     // K1 output (fp32)
__device__ __half g_t_h[(size_t)BB * DD];   // t_norm, fp16
__device__ __half g_v_h[(size_t)BB * DD];   // v_sel_norm, fp16

// ---------------------------------------------------------------------------
// PTX helpers (all sm_80-baseline: legal on compute_103)
// ---------------------------------------------------------------------------
__device__ __forceinline__ uint32_t smem_u32(const void* p) {
    uint32_t a;
    asm("{ .reg .u64 t; cvta.to.shared.u64 t, %1; cvt.u32.u64 %0, t; }" : "=r"(a) : "l"(p));
    return a;
}

#define CP_ASYNC16(saddr, gptr) \
    asm volatile("cp.async.cg.shared.global [%0], [%1], 16;" :: "r"(saddr), "l"(gptr))
#define CP_COMMIT() asm volatile("cp.async.commit_group;" ::: "memory")
#define CP_WAIT(n)  asm volatile("cp.async.wait_group %0;" :: "n"(n) : "memory")

#define LDSM4(r, addr) \
    asm volatile("ldmatrix.sync.aligned.m8n8.x4.shared.b16 {%0,%1,%2,%3}, [%4];" \
        : "=r"((r)[0]), "=r"((r)[1]), "=r"((r)[2]), "=r"((r)[3]) : "r"(addr))

#define MMA16816(d, a, b) \
    asm volatile("mma.sync.aligned.m16n8k16.row.col.f32.f16.f16.f32 " \
        "{%0,%1,%2,%3}, {%4,%5,%6,%7}, {%8,%9}, {%0,%1,%2,%3};" \
        : "+f"((d)[0]), "+f"((d)[1]), "+f"((d)[2]), "+f"((d)[3]) \
        : "r"((a)[0]), "r"((a)[1]), "r"((a)[2]), "r"((a)[3]), \
          "r"((b)[0]), "r"((b)[1]))

__device__ __forceinline__ unsigned packh(__half a, __half b) {
    __half2 t = __halves2half2(a, b);
    return *reinterpret_cast<unsigned*>(&t);
}

// ---------------------------------------------------------------------------
// Smem geometry: tiles of 128 rows x 32 halves, rows padded to 40 halves
// (80 B; m*5 mod 8 is a permutation -> LDSM conflict-free).
// ---------------------------------------------------------------------------
#define PITCH_B   80
#define TILE_B    (128 * PITCH_B)      // 10240 bytes

// ===========================================================================
// K1: fused-split fp32-input NT GEMM, 3-product fp16 split (err ~2^-22),
// tanh(x + bias) epilogue.  C[M,N] = tanh(A[M,K] @ B[N,K]^T + bias).
// 512 threads, warp grid 4x4, warp tile 32x32, block 128x128, BK=32.
// Loader: LDG fp32 -> split hi/lo fp16 in regs -> STS (double-buffered).
// ===========================================================================
__global__ __launch_bounds__(512) void mma_nt_f32(
    const float* __restrict__ A, const float* __restrict__ B,
    const float* __restrict__ bias, float* __restrict__ C,
    int M, int N, int K)
{
    extern __shared__ char smem[];
    const int tid  = threadIdx.x;
    const int lane = tid & 31;
    const int wid  = tid >> 5;       // 0..15
    const int wm   = wid >> 2;       // 0..3
    const int wn   = wid & 3;        // 0..3
    const int bm   = blockIdx.y * 128;
    const int bn   = blockIdx.x * 128;
    const uint32_t sb = smem_u32(smem);

    float acc[2][4][4];
    #pragma unroll
    for (int i = 0; i < 2; i++)
        #pragma unroll
        for (int j = 0; j < 4; j++)
            #pragma unroll
            for (int k = 0; k < 4; k++) acc[i][j][k] = 0.f;

    // loader mapping: slot = tid (+512); row = slot/8 (0..127), q = slot&7
    const int lrow = tid >> 3;        // 0..63; second slot adds +64 rows
    const int lq   = tid & 7;         // float4 index within 32-float row
    const float* Ap0 = A + (size_t)(bm + lrow) * K + lq * 4;
    const float* Ap1 = A + (size_t)(bm + lrow + 64) * K + lq * 4;
    const float* Bp0 = B + (size_t)(bn + lrow) * K + lq * 4;
    const float* Bp1 = B + (size_t)(bn + lrow + 64) * K + lq * 4;

    float4 ra[2], rb[2];
    auto ldg_stage = [&](int kt) {
        const int k0 = kt * 32;
        ra[0] = *(const float4*)(Ap0 + k0);
        ra[1] = *(const float4*)(Ap1 + k0);
        rb[0] = *(const float4*)(Bp0 + k0);
        rb[1] = *(const float4*)(Bp1 + k0);
    };
    // tiles per stage: [Ah, Al, Bh, Bl]
    auto sts_stage = [&](int stage) {
        const uint32_t base = (uint32_t)stage * 4 * TILE_B;
        #pragma unroll
        for (int it = 0; it < 2; it++) {
            const uint32_t o = base + (uint32_t)(lrow + it * 64) * PITCH_B + (uint32_t)lq * 8;
            float fa[4] = { ra[it].x, ra[it].y, ra[it].z, ra[it].w };
            float fb[4] = { rb[it].x, rb[it].y, rb[it].z, rb[it].w };
            __half ha[4], la[4], hb[4], lb[4];
            #pragma unroll
            for (int i = 0; i < 4; i++) {
                ha[i] = __float2half_rn(fa[i]);
                la[i] = __float2half_rn(fa[i] - __half2float(ha[i]));
                hb[i] = __float2half_rn(fb[i]);
                lb[i] = __float2half_rn(fb[i] - __half2float(hb[i]));
            }
            *(uint2*)(smem + 0 * TILE_B + o) = make_uint2(packh(ha[0], ha[1]), packh(ha[2], ha[3]));
            *(uint2*)(smem + 1 * TILE_B + o) = make_uint2(packh(la[0], la[1]), packh(la[2], la[3]));
            *(uint2*)(smem + 2 * TILE_B + o) = make_uint2(packh(hb[0], hb[1]), packh(hb[2], hb[3]));
            *(uint2*)(smem + 3 * TILE_B + o) = make_uint2(packh(lb[0], lb[1]), packh(lb[2], lb[3]));
        }
    };

    const uint32_t aoff = (uint32_t)(wm * 32 + (lane & 15)) * PITCH_B + ((lane >> 4) * 16);
    const uint32_t boff = (uint32_t)(wn * 32 + (lane & 7) + ((lane & 16) ? 8 : 0)) * PITCH_B
                        + (((lane >> 3) & 1) * 16);

    const int nk = K >> 5;
    ldg_stage(0);
    sts_stage(0);
    __syncthreads();

    for (int kt = 0; kt < nk; kt++) {
        if (kt + 1 < nk) ldg_stage(kt + 1);

        const uint32_t stg = (uint32_t)(kt & 1) * 4 * TILE_B;
        const uint32_t aAh = sb + stg + 0 * TILE_B;
        const uint32_t aAl = sb + stg + 1 * TILE_B;
        const uint32_t aBh = sb + stg + 2 * TILE_B;
        const uint32_t aBl = sb + stg + 3 * TILE_B;

        #pragma unroll
        for (int ks = 0; ks < 2; ks++) {
            uint32_t ah[2][4], al[2][4], bh[4][2], bl[4][2];
            #pragma unroll
            for (int mf = 0; mf < 2; mf++) {
                LDSM4(ah[mf], aAh + aoff + (uint32_t)mf * 16 * PITCH_B + ks * 32);
                LDSM4(al[mf], aAl + aoff + (uint32_t)mf * 16 * PITCH_B + ks * 32);
            }
            #pragma unroll
            for (int p = 0; p < 2; p++) {
                uint32_t r[4];
                LDSM4(r, aBh + boff + (uint32_t)p * 16 * PITCH_B + ks * 32);
                bh[2*p][0] = r[0]; bh[2*p][1] = r[1];
                bh[2*p+1][0] = r[2]; bh[2*p+1][1] = r[3];
                LDSM4(r, aBl + boff + (uint32_t)p * 16 * PITCH_B + ks * 32);
                bl[2*p][0] = r[0]; bl[2*p][1] = r[1];
                bl[2*p+1][0] = r[2]; bl[2*p+1][1] = r[3];
            }
            #pragma unroll
            for (int mf = 0; mf < 2; mf++)
                #pragma unroll
                for (int nf = 0; nf < 4; nf++) {
                    MMA16816(acc[mf][nf], ah[mf], bh[nf]);
                    MMA16816(acc[mf][nf], ah[mf], bl[nf]);
                    MMA16816(acc[mf][nf], al[mf], bh[nf]);
                }
        }

        if (kt + 1 < nk) {
            sts_stage((kt + 1) & 1);
            __syncthreads();
        }
    }

    // ---- epilogue: tanh(x + bias), direct global stores ----
    const int er = bm + wm * 32 + (lane >> 2);
    const int ec = bn + wn * 32 + (lane & 3) * 2;
    #pragma unroll
    for (int mf = 0; mf < 2; mf++)
        #pragma unroll
        for (int nf = 0; nf < 4; nf++) {
            const int r = er + mf * 16;
            const int c = ec + nf * 8;
            const float b0 = __ldg(&bias[c]), b1 = __ldg(&bias[c + 1]);
            float v0 = tanhf(acc[mf][nf][0] + b0);
            float v1 = tanhf(acc[mf][nf][1] + b1);
            float v2 = tanhf(acc[mf][nf][2] + b0);
            float v3 = tanhf(acc[mf][nf][3] + b1);
            *(float2*)&C[(size_t)r * N + c]       = make_float2(v0, v1);
            *(float2*)&C[(size_t)(r + 8) * N + c] = make_float2(v2, v3);
        }
}

// ===========================================================================
// K3: plain fp16 NT GEMM via mma.sync, fp32 accum. 512 threads, warp grid
// 4x4, block 128x128, BK=32. cp.async double-buffered. 40KB smem -> 2 CTA/SM.
// ===========================================================================
__global__ __launch_bounds__(512) void mma_nt_h(
    const __half* __restrict__ A, const __half* __restrict__ B,
    float* __restrict__ C, int M, int N, int K)
{
    extern __shared__ char smem[];
    const int tid  = threadIdx.x;
    const int lane = tid & 31;
    const int wid  = tid >> 5;
    const int wm   = wid >> 2;
    const int wn   = wid & 3;
    const int bm   = blockIdx.y * 128;
    const int bn   = blockIdx.x * 128;
    const uint32_t sb = smem_u32(smem);

    float acc[2][4][4];
    #pragma unroll
    for (int i = 0; i < 2; i++)
        #pragma unroll
        for (int j = 0; j < 4; j++)
            #pragma unroll
            for (int k = 0; k < 4; k++) acc[i][j][k] = 0.f;

    const __half* srcs[2] = { A, B };
    const int r0s[2] = { bm, bn };
    const int lrow = tid >> 2;           // 0..127
    const int lcc  = (tid & 3) * 16;     // byte col within 64B row

    auto prefetch = [&](int kt, int stage) {
        const int k0b = kt * 64;
        #pragma unroll
        for (int t = 0; t < 2; t++) {
            const uint32_t d = sb + (uint32_t)(stage * 2 + t) * TILE_B
                             + (uint32_t)lrow * PITCH_B + lcc;
            const char* g = (const char*)srcs[t] + ((size_t)(r0s[t] + lrow) * K) * 2 + k0b + lcc;
            CP_ASYNC16(d, g);
        }
    };

    const uint32_t aoff = (uint32_t)(wm * 32 + (lane & 15)) * PITCH_B + ((lane >> 4) * 16);
    const uint32_t boff = (uint32_t)(wn * 32 + (lane & 7) + ((lane & 16) ? 8 : 0)) * PITCH_B
                        + (((lane >> 3) & 1) * 16);

    const int nk = K >> 5;
    prefetch(0, 0);
    CP_COMMIT();

    for (int kt = 0; kt < nk; kt++) {
        if (kt + 1 < nk) { prefetch(kt + 1, (kt + 1) & 1); CP_COMMIT(); CP_WAIT(1); }
        else             { CP_WAIT(0); }
        __syncthreads();

        const uint32_t stg = (uint32_t)(kt & 1) * 2 * TILE_B;
        const uint32_t aA = sb + stg + 0 * TILE_B;
        const uint32_t aB = sb + stg + 1 * TILE_B;

        #pragma unroll
        for (int ks = 0; ks < 2; ks++) {
            uint32_t ah[2][4], bh[4][2];
            #pragma unroll
            for (int mf = 0; mf < 2; mf++)
                LDSM4(ah[mf], aA + aoff + (uint32_t)mf * 16 * PITCH_B + ks * 32);
            #pragma unroll
            for (int p = 0; p < 2; p++) {
                uint32_t r[4];
                LDSM4(r, aB + boff + (uint32_t)p * 16 * PITCH_B + ks * 32);
                bh[2*p][0] = r[0]; bh[2*p][1] = r[1];
                bh[2*p+1][0] = r[2]; bh[2*p+1][1] = r[3];
            }
            #pragma unroll
            for (int mf = 0; mf < 2; mf++)
                #pragma unroll
                for (int nf = 0; nf < 4; nf++)
                    MMA16816(acc[mf][nf], ah[mf], bh[nf]);
        }
        __syncthreads();
    }

    const int er = bm + wm * 32 + (lane >> 2);
    const int ec = bn + wn * 32 + (lane & 3) * 2;
    #pragma unroll
    for (int mf = 0; mf < 2; mf++)
        #pragma unroll
        for (int nf = 0; nf < 4; nf++) {
            const int r = er + mf * 16;
            const int c = ec + nf * 8;
            *(float2*)&C[(size_t)r * N + c]       = make_float2(acc[mf][nf][0], acc[mf][nf][1]);
            *(float2*)&C[(size_t)(r + 8) * N + c] = make_float2(acc[mf][nf][2], acc[mf][nf][3]);
        }
}

// ---------------------------------------------------------------------------
// Per-batch select: normalize t row, argmax_j (t . v_j)/||v_j|| (pure fp32 —
// no selection-flip risk), emit fp16 t_norm and fp16 v_sel_norm.
// ---------------------------------------------------------------------------
__global__ __launch_bounds__(256) void select_kernel(const float* __restrict__ vis)
{
    __shared__ float ts[DD];
    __shared__ float s_sim[8];
    __shared__ int   s_j[8];
    __shared__ float s_nn[8];
    __shared__ float s_scale;
    __shared__ int   s_bj;

    const int b    = blockIdx.x;
    const int tid  = threadIdx.x;
    const int lane = tid & 31;
    const int w    = tid >> 5;

    // ---- load + normalize t row ----
    const float* trow = g_t + (size_t)b * DD;
    float4 tv = ((const float4*)trow)[tid];
    float ss = tv.x * tv.x + tv.y * tv.y + tv.z * tv.z + tv.w * tv.w;
    #pragma unroll
    for (int o = 16; o; o >>= 1) ss += __shfl_xor_sync(0xffffffffu, ss, o);
    if (lane == 0) s_nn[w] = ss;
    __syncthreads();
    if (tid == 0) {
        float tot = 0.f;
        #pragma unroll
        for (int i = 0; i < 8; i++) tot += s_nn[i];
        s_scale = 1.0f / fmaxf(sqrtf(tot), 1e-12f);
    }
    __syncthreads();
    {
        const float inv = s_scale;
        tv.x *= inv; tv.y *= inv; tv.z *= inv; tv.w *= inv;
        ((float4*)ts)[tid] = tv;
        __half2* H = (__half2*)(g_t_h + (size_t)b * DD);
        H[2 * tid]     = __halves2half2(__float2half_rn(tv.x), __float2half_rn(tv.y));
        H[2 * tid + 1] = __halves2half2(__float2half_rn(tv.z), __float2half_rn(tv.w));
    }
    __syncthreads();

    // ---- stream v[b] (evict-first), fused dot + norm^2, warp-strided ----
    float best = -1e30f;
    int   bj   = 0x7fffffff;
    float bnn  = 1.0f;
    const float4* tsv = (const float4*)ts;

    for (int j = w; j < NN; j += 8) {
        const float4* vr = (const float4*)(vis + ((size_t)b * NN + j) * DD);
        float dot = 0.f, nn = 0.f;
        #pragma unroll
        for (int i = 0; i < 8; i++) {
            float4 x  = __ldcs(&vr[lane + 32 * i]);
            float4 tt = tsv[lane + 32 * i];
            dot += x.x * tt.x; dot += x.y * tt.y; dot += x.z * tt.z; dot += x.w * tt.w;
            nn  += x.x * x.x;  nn  += x.y * x.y;  nn  += x.z * x.z;  nn  += x.w * x.w;
        }
        #pragma unroll
        for (int o = 16; o; o >>= 1) {
            dot += __shfl_xor_sync(0xffffffffu, dot, o);
            nn  += __shfl_xor_sync(0xffffffffu, nn, o);
        }
        const float sim = dot * rsqrtf(fmaxf(nn, 1e-24f));
        if (sim > best) { best = sim; bj = j; bnn = nn; }
    }
    if (lane == 0) { s_sim[w] = best; s_j[w] = bj; s_nn[w] = bnn; }
    __syncthreads();

    if (tid == 0) {
        float bs = s_sim[0]; int bjj = s_j[0]; float bn = s_nn[0];
        #pragma unroll
        for (int i = 1; i < 8; i++) {
            if (s_sim[i] > bs || (s_sim[i] == bs && s_j[i] < bjj)) {
                bs = s_sim[i]; bjj = s_j[i]; bn = s_nn[i];
            }
        }
        s_bj = bjj;
        s_scale = 1.0f / fmaxf(sqrtf(bn), 1e-12f);
    }
    __syncthreads();

    // ---- write fp16 normalized selected row (re-read = L2 hit) ----
    const int   jb = s_bj;
    const float sc = s_scale;
    const float4* vrb = (const float4*)(vis + ((size_t)b * NN + jb) * DD);
    float4 x4 = vrb[tid];
    __half2* H = (__half2*)(g_v_h + (size_t)b * DD);
    H[2 * tid]     = __halves2half2(__float2half_rn(x4.x * sc), __float2half_rn(x4.y * sc));
    H[2 * tid + 1] = __halves2half2(__float2half_rn(x4.z * sc), __float2half_rn(x4.w * sc));
}

// ---------------------------------------------------------------------------
// Launch
// ---------------------------------------------------------------------------
extern "C" void kernel_launch(void* const* d_in, const int* in_sizes, int n_in,
                              void* d_out, int out_size)
{
    const float* vis  = nullptr;
    const float* txt  = nullptr;
    const float* W    = nullptr;
    const float* bias = nullptr;
    for (int i = 0; i < n_in; i++) {
        const long long s = in_sizes[i];
        if      (s == (long long)BB * NN * DD) vis  = (const float*)d_in[i];
        else if (s == (long long)BB * DC)      txt  = (const float*)d_in[i];
        else if (s == (long long)DD * DC)      W    = (const float*)d_in[i];
        else if (s == (long long)DD)           bias = (const float*)d_in[i];
    }
    float* out = (float*)d_out;

    float *t_ptr;
    __half *th, *vh;
    cudaGetSymbolAddress((void**)&t_ptr, g_t);
    cudaGetSymbolAddress((void**)&th,  g_t_h);
    cudaGetSymbolAddress((void**)&vh,  g_v_h);

    const int smem4 = 2 * 4 * TILE_B;   // 81920 (K1: Ah,Al,Bh,Bl x 2 stages)
    const int smem2 = 2 * 2 * TILE_B;   // 40960 (K3: A,B x 2 stages)
    cudaFuncSetAttribute(mma_nt_f32, cudaFuncAttributeMaxDynamicSharedMemorySize, smem4);
    cudaFuncSetAttribute(mma_nt_h,   cudaFuncAttributeMaxDynamicSharedMemorySize, smem2);

    // K1: t = tanh(txt @ W^T + b)  [2048,1024], K=512  (fused fp32->hi/lo split)
    {
        dim3 grid(DD / 128, BB / 128);
        mma_nt_f32<<<grid, 512, smem4>>>(txt, W, bias, t_ptr, BB, DD, DC);
    }
    // K2: normalize t, fp32 argmax over patches, emit fp16 operands for K3
    select_kernel<<<BB, 256>>>(vis);
    // K3: out = t_norm @ v_sel^T  [2048,2048], K=1024  (fp16, err ~3e-4 global)
    {
        dim3 grid(BB / 128, BB / 128);
        mma_nt_h<<<grid, 512, smem2>>>(th, vh, out, BB, BB, DD);
    }
}

// round 9
// speedup vs baseline: 1.0003x; 1.0003x over previous
#include <cuda_runtime.h>
#include <cuda_fp16.h>
#include <cstdint>

// Problem dims
#define BB   2048
#define NN   196
#define DD   1024
#define DC   512

// ---------------------------------------------------------------------------
// Scratch (device globals; no allocation allowed)
// ---------------------------------------------------------------------------
__device__ float  g_t[(size_t)BB * DD];     // K1 output (fp32)
__device__ __half g_t_h[(size_t)BB * DD];   // t_norm, fp16
__device__ __half g_v_h[(size_t)BB * DD];   // v_sel_norm, fp16

// ---------------------------------------------------------------------------
// PTX helpers (all sm_80-baseline: legal on compute_103)
// ---------------------------------------------------------------------------
__device__ __forceinline__ uint32_t smem_u32(const void* p) {
    uint32_t a;
    asm("{ .reg .u64 t; cvta.to.shared.u64 t, %1; cvt.u32.u64 %0, t; }" : "=r"(a) : "l"(p));
    return a;
}

#define CP_ASYNC16(saddr, gptr) \
    asm volatile("cp.async.cg.shared.global [%0], [%1], 16;" :: "r"(saddr), "l"(gptr))
#define CP_COMMIT() asm volatile("cp.async.commit_group;" ::: "memory")
#define CP_WAIT(n)  asm volatile("cp.async.wait_group %0;" :: "n"(n) : "memory")

#define LDSM4(r, addr) \
    asm volatile("ldmatrix.sync.aligned.m8n8.x4.shared.b16 {%0,%1,%2,%3}, [%4];" \
        : "=r"((r)[0]), "=r"((r)[1]), "=r"((r)[2]), "=r"((r)[3]) : "r"(addr))

#define MMA16816(d, a, b) \
    asm volatile("mma.sync.aligned.m16n8k16.row.col.f32.f16.f16.f32 " \
        "{%0,%1,%2,%3}, {%4,%5,%6,%7}, {%8,%9}, {%0,%1,%2,%3};" \
        : "+f"((d)[0]), "+f"((d)[1]), "+f"((d)[2]), "+f"((d)[3]) \
        : "r"((a)[0]), "r"((a)[1]), "r"((a)[2]), "r"((a)[3]), \
          "r"((b)[0]), "r"((b)[1]))

__device__ __forceinline__ unsigned packh(__half a, __half b) {
    __half2 t = __halves2half2(a, b);
    return *reinterpret_cast<unsigned*>(&t);
}

// ---------------------------------------------------------------------------
// Smem geometry: tiles of 128 rows x 32 halves, rows padded to 40 halves
// (80 B; m*5 mod 8 is a permutation -> LDSM conflict-free).
// ---------------------------------------------------------------------------
#define PITCH_B   80
#define TILE_B    (128 * PITCH_B)      // 10240 bytes

// ===========================================================================
// K1: fused-split fp32-input NT GEMM, 3-product fp16 split (err ~2^-22),
// tanh(x + bias) epilogue.  C[M,N] = tanh(A[M,K] @ B[N,K]^T + bias).
// 512 threads, warp grid 4x4, warp tile 32x32, block 128x128, BK=32.
// (R8-measured best: 24.8us, tensor=41.7%)
// ===========================================================================
__global__ __launch_bounds__(512) void mma_nt_f32(
    const float* __restrict__ A, const float* __restrict__ B,
    const float* __restrict__ bias, float* __restrict__ C,
    int M, int N, int K)
{
    extern __shared__ char smem[];
    const int tid  = threadIdx.x;
    const int lane = tid & 31;
    const int wid  = tid >> 5;       // 0..15
    const int wm   = wid >> 2;       // 0..3
    const int wn   = wid & 3;        // 0..3
    const int bm   = blockIdx.y * 128;
    const int bn   = blockIdx.x * 128;
    const uint32_t sb = smem_u32(smem);

    float acc[2][4][4];
    #pragma unroll
    for (int i = 0; i < 2; i++)
        #pragma unroll
        for (int j = 0; j < 4; j++)
            #pragma unroll
            for (int k = 0; k < 4; k++) acc[i][j][k] = 0.f;

    // loader mapping: row = tid/8 (0..63, +64 for slot 2), q = tid&7
    const int lrow = tid >> 3;
    const int lq   = tid & 7;
    const float* Ap0 = A + (size_t)(bm + lrow) * K + lq * 4;
    const float* Ap1 = A + (size_t)(bm + lrow + 64) * K + lq * 4;
    const float* Bp0 = B + (size_t)(bn + lrow) * K + lq * 4;
    const float* Bp1 = B + (size_t)(bn + lrow + 64) * K + lq * 4;

    float4 ra[2], rb[2];
    auto ldg_stage = [&](int kt) {
        const int k0 = kt * 32;
        ra[0] = *(const float4*)(Ap0 + k0);
        ra[1] = *(const float4*)(Ap1 + k0);
        rb[0] = *(const float4*)(Bp0 + k0);
        rb[1] = *(const float4*)(Bp1 + k0);
    };
    auto sts_stage = [&](int stage) {
        const uint32_t base = (uint32_t)stage * 4 * TILE_B;
        #pragma unroll
        for (int it = 0; it < 2; it++) {
            const uint32_t o = base + (uint32_t)(lrow + it * 64) * PITCH_B + (uint32_t)lq * 8;
            float fa[4] = { ra[it].x, ra[it].y, ra[it].z, ra[it].w };
            float fb[4] = { rb[it].x, rb[it].y, rb[it].z, rb[it].w };
            __half ha[4], la[4], hb[4], lb[4];
            #pragma unroll
            for (int i = 0; i < 4; i++) {
                ha[i] = __float2half_rn(fa[i]);
                la[i] = __float2half_rn(fa[i] - __half2float(ha[i]));
                hb[i] = __float2half_rn(fb[i]);
                lb[i] = __float2half_rn(fb[i] - __half2float(hb[i]));
            }
            *(uint2*)(smem + 0 * TILE_B + o) = make_uint2(packh(ha[0], ha[1]), packh(ha[2], ha[3]));
            *(uint2*)(smem + 1 * TILE_B + o) = make_uint2(packh(la[0], la[1]), packh(la[2], la[3]));
            *(uint2*)(smem + 2 * TILE_B + o) = make_uint2(packh(hb[0], hb[1]), packh(hb[2], hb[3]));
            *(uint2*)(smem + 3 * TILE_B + o) = make_uint2(packh(lb[0], lb[1]), packh(lb[2], lb[3]));
        }
    };

    const uint32_t aoff = (uint32_t)(wm * 32 + (lane & 15)) * PITCH_B + ((lane >> 4) * 16);
    const uint32_t boff = (uint32_t)(wn * 32 + (lane & 7) + ((lane & 16) ? 8 : 0)) * PITCH_B
                        + (((lane >> 3) & 1) * 16);

    const int nk = K >> 5;
    ldg_stage(0);
    sts_stage(0);
    __syncthreads();

    for (int kt = 0; kt < nk; kt++) {
        if (kt + 1 < nk) ldg_stage(kt + 1);

        const uint32_t stg = (uint32_t)(kt & 1) * 4 * TILE_B;
        const uint32_t aAh = sb + stg + 0 * TILE_B;
        const uint32_t aAl = sb + stg + 1 * TILE_B;
        const uint32_t aBh = sb + stg + 2 * TILE_B;
        const uint32_t aBl = sb + stg + 3 * TILE_B;

        #pragma unroll
        for (int ks = 0; ks < 2; ks++) {
            uint32_t ah[2][4], al[2][4], bh[4][2], bl[4][2];
            #pragma unroll
            for (int mf = 0; mf < 2; mf++) {
                LDSM4(ah[mf], aAh + aoff + (uint32_t)mf * 16 * PITCH_B + ks * 32);
                LDSM4(al[mf], aAl + aoff + (uint32_t)mf * 16 * PITCH_B + ks * 32);
            }
            #pragma unroll
            for (int p = 0; p < 2; p++) {
                uint32_t r[4];
                LDSM4(r, aBh + boff + (uint32_t)p * 16 * PITCH_B + ks * 32);
                bh[2*p][0] = r[0]; bh[2*p][1] = r[1];
                bh[2*p+1][0] = r[2]; bh[2*p+1][1] = r[3];
                LDSM4(r, aBl + boff + (uint32_t)p * 16 * PITCH_B + ks * 32);
                bl[2*p][0] = r[0]; bl[2*p][1] = r[1];
                bl[2*p+1][0] = r[2]; bl[2*p+1][1] = r[3];
            }
            #pragma unroll
            for (int mf = 0; mf < 2; mf++)
                #pragma unroll
                for (int nf = 0; nf < 4; nf++) {
                    MMA16816(acc[mf][nf], ah[mf], bh[nf]);
                    MMA16816(acc[mf][nf], ah[mf], bl[nf]);
                    MMA16816(acc[mf][nf], al[mf], bh[nf]);
                }
        }

        if (kt + 1 < nk) {
            sts_stage((kt + 1) & 1);
            __syncthreads();
        }
    }

    // ---- epilogue: tanh(x + bias), direct global stores ----
    const int er = bm + wm * 32 + (lane >> 2);
    const int ec = bn + wn * 32 + (lane & 3) * 2;
    #pragma unroll
    for (int mf = 0; mf < 2; mf++)
        #pragma unroll
        for (int nf = 0; nf < 4; nf++) {
            const int r = er + mf * 16;
            const int c = ec + nf * 8;
            const float b0 = __ldg(&bias[c]), b1 = __ldg(&bias[c + 1]);
            float v0 = tanhf(acc[mf][nf][0] + b0);
            float v1 = tanhf(acc[mf][nf][1] + b1);
            float v2 = tanhf(acc[mf][nf][2] + b0);
            float v3 = tanhf(acc[mf][nf][3] + b1);
            *(float2*)&C[(size_t)r * N + c]       = make_float2(v0, v1);
            *(float2*)&C[(size_t)(r + 8) * N + c] = make_float2(v2, v3);
        }
}

// ===========================================================================
// K3: plain fp16 NT GEMM via mma.sync, fp32 accum. 256 threads, warp grid
// 2x4, warp tile 64x32 (R7-measured best config for the 1-product GEMM:
// better LDSM-per-MMA amortization than 4x4). cp.async double-buffered.
// ===========================================================================
__global__ __launch_bounds__(256) void mma_nt_h(
    const __half* __restrict__ A, const __half* __restrict__ B,
    float* __restrict__ C, int M, int N, int K)
{
    extern __shared__ char smem[];
    const int tid  = threadIdx.x;
    const int lane = tid & 31;
    const int wid  = tid >> 5;
    const int wm   = wid >> 2;       // 0..1
    const int wn   = wid & 3;        // 0..3
    const int bm   = blockIdx.y * 128;
    const int bn   = blockIdx.x * 128;
    const uint32_t sb = smem_u32(smem);

    float acc[4][4][4];
    #pragma unroll
    for (int i = 0; i < 4; i++)
        #pragma unroll
        for (int j = 0; j < 4; j++)
            #pragma unroll
            for (int k = 0; k < 4; k++) acc[i][j][k] = 0.f;

    const __half* srcs[2] = { A, B };
    const int r0s[2] = { bm, bn };
    const int lrow0 = tid >> 2;
    const int lcc   = (tid & 3) * 16;

    auto prefetch = [&](int kt, int stage) {
        const int k0b = kt * 64;
        #pragma unroll
        for (int t = 0; t < 2; t++) {
            const uint32_t db = sb + (uint32_t)(stage * 2 + t) * TILE_B;
            const char* s = (const char*)srcs[t];
            #pragma unroll
            for (int it = 0; it < 2; it++) {
                const int row = lrow0 + it * 64;
                const uint32_t d = db + (uint32_t)row * PITCH_B + lcc;
                const char* g = s + ((size_t)(r0s[t] + row) * K) * 2 + k0b + lcc;
                CP_ASYNC16(d, g);
            }
        }
    };

    const uint32_t aoff = (uint32_t)(wm * 64 + (lane & 15)) * PITCH_B + ((lane >> 4) * 16);
    const uint32_t boff = (uint32_t)(wn * 32 + (lane & 7) + ((lane & 16) ? 8 : 0)) * PITCH_B
                        + (((lane >> 3) & 1) * 16);

    const int nk = K >> 5;
    prefetch(0, 0);
    CP_COMMIT();

    for (int kt = 0; kt < nk; kt++) {
        if (kt + 1 < nk) { prefetch(kt + 1, (kt + 1) & 1); CP_COMMIT(); CP_WAIT(1); }
        else             { CP_WAIT(0); }
        __syncthreads();

        const uint32_t stg = (uint32_t)(kt & 1) * 2 * TILE_B;
        const uint32_t aA = sb + stg + 0 * TILE_B;
        const uint32_t aB = sb + stg + 1 * TILE_B;

        #pragma unroll
        for (int ks = 0; ks < 2; ks++) {
            uint32_t ah[4][4], bh[4][2];
            #pragma unroll
            for (int mf = 0; mf < 4; mf++)
                LDSM4(ah[mf], aA + aoff + (uint32_t)mf * 16 * PITCH_B + ks * 32);
            #pragma unroll
            for (int p = 0; p < 2; p++) {
                uint32_t r[4];
                LDSM4(r, aB + boff + (uint32_t)p * 16 * PITCH_B + ks * 32);
                bh[2*p][0] = r[0]; bh[2*p][1] = r[1];
                bh[2*p+1][0] = r[2]; bh[2*p+1][1] = r[3];
            }
            #pragma unroll
            for (int mf = 0; mf < 4; mf++)
                #pragma unroll
                for (int nf = 0; nf < 4; nf++)
                    MMA16816(acc[mf][nf], ah[mf], bh[nf]);
        }
        __syncthreads();
    }

    const int er = bm + wm * 64 + (lane >> 2);
    const int ec = bn + wn * 32 + (lane & 3) * 2;
    #pragma unroll
    for (int mf = 0; mf < 4; mf++)
        #pragma unroll
        for (int nf = 0; nf < 4; nf++) {
            const int r = er + mf * 16;
            const int c = ec + nf * 8;
            *(float2*)&C[(size_t)r * N + c]       = make_float2(acc[mf][nf][0], acc[mf][nf][1]);
            *(float2*)&C[(size_t)(r + 8) * N + c] = make_float2(acc[mf][nf][2], acc[mf][nf][3]);
        }
}

// ---------------------------------------------------------------------------
// Per-batch select: normalize t row, argmax_j (t . v_j)/||v_j|| (pure fp32 —
// no selection-flip risk), emit fp16 t_norm and fp16 v_sel_norm.
// ---------------------------------------------------------------------------
__global__ __launch_bounds__(256) void select_kernel(const float* __restrict__ vis)
{
    __shared__ float ts[DD];
    __shared__ float s_sim[8];
    __shared__ int   s_j[8];
    __shared__ float s_nn[8];
    __shared__ float s_scale;
    __shared__ int   s_bj;

    const int b    = blockIdx.x;
    const int tid  = threadIdx.x;
    const int lane = tid & 31;
    const int w    = tid >> 5;

    // ---- load + normalize t row ----
    const float* trow = g_t + (size_t)b * DD;
    float4 tv = ((const float4*)trow)[tid];
    float ss = tv.x * tv.x + tv.y * tv.y + tv.z * tv.z + tv.w * tv.w;
    #pragma unroll
    for (int o = 16; o; o >>= 1) ss += __shfl_xor_sync(0xffffffffu, ss, o);
    if (lane == 0) s_nn[w] = ss;
    __syncthreads();
    if (tid == 0) {
        float tot = 0.f;
        #pragma unroll
        for (int i = 0; i < 8; i++) tot += s_nn[i];
        s_scale = 1.0f / fmaxf(sqrtf(tot), 1e-12f);
    }
    __syncthreads();
    {
        const float inv = s_scale;
        tv.x *= inv; tv.y *= inv; tv.z *= inv; tv.w *= inv;
        ((float4*)ts)[tid] = tv;
        __half2* H = (__half2*)(g_t_h + (size_t)b * DD);
        H[2 * tid]     = __halves2half2(__float2half_rn(tv.x), __float2half_rn(tv.y));
        H[2 * tid + 1] = __halves2half2(__float2half_rn(tv.z), __float2half_rn(tv.w));
    }
    __syncthreads();

    // ---- stream v[b] (evict-first), fused dot + norm^2, warp-strided ----
    float best = -1e30f;
    int   bj   = 0x7fffffff;
    float bnn  = 1.0f;
    const float4* tsv = (const float4*)ts;

    for (int j = w; j < NN; j += 8) {
        const float4* vr = (const float4*)(vis + ((size_t)b * NN + j) * DD);
        float dot = 0.f, nn = 0.f;
        #pragma unroll
        for (int i = 0; i < 8; i++) {
            float4 x  = __ldcs(&vr[lane + 32 * i]);
            float4 tt = tsv[lane + 32 * i];
            dot += x.x * tt.x; dot += x.y * tt.y; dot += x.z * tt.z; dot += x.w * tt.w;
            nn  += x.x * x.x;  nn  += x.y * x.y;  nn  += x.z * x.z;  nn  += x.w * x.w;
        }
        #pragma unroll
        for (int o = 16; o; o >>= 1) {
            dot += __shfl_xor_sync(0xffffffffu, dot, o);
            nn  += __shfl_xor_sync(0xffffffffu, nn, o);
        }
        const float sim = dot * rsqrtf(fmaxf(nn, 1e-24f));
        if (sim > best) { best = sim; bj = j; bnn = nn; }
    }
    if (lane == 0) { s_sim[w] = best; s_j[w] = bj; s_nn[w] = bnn; }
    __syncthreads();

    if (tid == 0) {
        float bs = s_sim[0]; int bjj = s_j[0]; float bn = s_nn[0];
        #pragma unroll
        for (int i = 1; i < 8; i++) {
            if (s_sim[i] > bs || (s_sim[i] == bs && s_j[i] < bjj)) {
                bs = s_sim[i]; bjj = s_j[i]; bn = s_nn[i];
            }
        }
        s_bj = bjj;
        s_scale = 1.0f / fmaxf(sqrtf(bn), 1e-12f);
    }
    __syncthreads();

    // ---- write fp16 normalized selected row (re-read = L2 hit) ----
    const int   jb = s_bj;
    const float sc = s_scale;
    const float4* vrb = (const float4*)(vis + ((size_t)b * NN + jb) * DD);
    float4 x4 = vrb[tid];
    __half2* H = (__half2*)(g_v_h + (size_t)b * DD);
    H[2 * tid]     = __halves2half2(__float2half_rn(x4.x * sc), __float2half_rn(x4.y * sc));
    H[2 * tid + 1] = __halves2half2(__float2half_rn(x4.z * sc), __float2half_rn(x4.w * sc));
}

// ---------------------------------------------------------------------------
// Launch
// ---------------------------------------------------------------------------
extern "C" void kernel_launch(void* const* d_in, const int* in_sizes, int n_in,
                              void* d_out, int out_size)
{
    const float* vis  = nullptr;
    const float* txt  = nullptr;
    const float* W    = nullptr;
    const float* bias = nullptr;
    for (int i = 0; i < n_in; i++) {
        const long long s = in_sizes[i];
        if      (s == (long long)BB * NN * DD) vis  = (const float*)d_in[i];
        else if (s == (long long)BB * DC)      txt  = (const float*)d_in[i];
        else if (s == (long long)DD * DC)      W    = (const float*)d_in[i];
        else if (s == (long long)DD)           bias = (const float*)d_in[i];
    }
    float* out = (float*)d_out;

    float *t_ptr;
    __half *th, *vh;
    cudaGetSymbolAddress((void**)&t_ptr, g_t);
    cudaGetSymbolAddress((void**)&th,  g_t_h);
    cudaGetSymbolAddress((void**)&vh,  g_v_h);

    const int smem4 = 2 * 4 * TILE_B;   // 81920 (K1: Ah,Al,Bh,Bl x 2 stages)
    const int smem2 = 2 * 2 * TILE_B;   // 40960 (K3: A,B x 2 stages)
    cudaFuncSetAttribute(mma_nt_f32, cudaFuncAttributeMaxDynamicSharedMemorySize, smem4);
    cudaFuncSetAttribute(mma_nt_h,   cudaFuncAttributeMaxDynamicSharedMemorySize, smem2);

    // K1: t = tanh(txt @ W^T + b)  [2048,1024], K=512  (fused fp32->hi/lo split)
    {
        dim3 grid(DD / 128, BB / 128);
        mma_nt_f32<<<grid, 512, smem4>>>(txt, W, bias, t_ptr, BB, DD, DC);
    }
    // K2: normalize t, fp32 argmax over patches, emit fp16 operands for K3
    select_kernel<<<BB, 256>>>(vis);
    // K3: out = t_norm @ v_sel^T  [2048,2048], K=1024  (fp16, err ~3e-4 global)
    {
        dim3 grid(BB / 128, BB / 128);
        mma_nt_h<<<grid, 256, smem2>>>(th, vh, out, BB, BB, DD);
    }
}